// round 5
// baseline (speedup 1.0000x reference)
#include <cuda_runtime.h>

#define HBV   20
#define DV    40
#define WPAD  28          // padded weight row: 112B, float4-aligned, conflict-free
#define WARPS 4

__global__ __launch_bounds__(128)
void ende_kernel(const float* __restrict__ x,
                 const float* __restrict__ w1g,
                 const float* __restrict__ w2g,
                 const float* __restrict__ w3g,
                 const float* __restrict__ w4g,
                 float* __restrict__ out_vec,
                 float* __restrict__ out_jt)
{
    __shared__ __align__(16) float sw1[HBV * WPAD];
    __shared__ __align__(16) float sw2[HBV * WPAD];
    __shared__ __align__(16) float sw3[HBV * WPAD];
    __shared__ __align__(16) float sw4[HBV * WPAD];
    __shared__ __align__(16) float p1s[WARPS][HBV];
    __shared__ __align__(16) float s2s[WARPS][HBV];
    __shared__ __align__(16) float e2s[WARPS][HBV];
    __shared__ __align__(16) float j21s[WARPS][HBV * HBV];  // rows of 20f (80B)

    const int tid = threadIdx.x;

    // Stage weights into padded smem (once per block)
    for (int idx = tid; idx < HBV * HBV; idx += 128) {
        int r = idx / HBV, c = idx % HBV;
        sw1[r * WPAD + c] = w1g[idx];
        sw2[r * WPAD + c] = w2g[idx];
        sw3[r * WPAD + c] = w3g[idx];
        sw4[r * WPAD + c] = w4g[idx];
    }
    __syncthreads();

    const int w = tid >> 5;
    const int l = tid & 31;
    const long long b = (long long)blockIdx.x * WARPS + w;
    const float* xr = x + b * DV;
    float* jt = out_jt + b * (DV * DV);

    const bool act = (l < HBV);
    const int ll = act ? l : 0;

    // ---- load x; publish p1 vector ----
    float p1_own = 0.f, p2_own = 0.f;
    if (act) {
        p1_own = xr[l];
        p2_own = xr[HBV + l];
        p1s[w][l] = p1_own;
    }
    __syncwarp();

    // ---- Stage A: lane l -> f1[l], f2[l] (row-l matvec) ----
    float e2_own = 0.f, s2_own = 0.f, b1o = 0.f, b2o = 0.f;
    {
        float a1 = 0.f, a2 = 0.f;
        const float4* r1 = (const float4*)(sw1 + ll * WPAD);
        const float4* r2 = (const float4*)(sw2 + ll * WPAD);
        const float4* pv = (const float4*)(p1s[w]);
        #pragma unroll
        for (int g = 0; g < 5; g++) {
            float4 A = r1[g], Bv = r2[g], P = pv[g];
            a1 = fmaf(A.x,  P.x, a1); a1 = fmaf(A.y,  P.y, a1);
            a1 = fmaf(A.z,  P.z, a1); a1 = fmaf(A.w,  P.w, a1);
            a2 = fmaf(Bv.x, P.x, a2); a2 = fmaf(Bv.y, P.y, a2);
            a2 = fmaf(Bv.z, P.z, a2); a2 = fmaf(Bv.w, P.w, a2);
        }
        float f1 = tanhf(a1);
        float f2 = tanhf(a2);
        e2_own = expf(f2);
        float p2e = p2_own * e2_own;
        s2_own = p2e + f1;
        b1o = 1.f - f1 * f1;
        b2o = p2e * (1.f - f2 * f2);
        if (act) { s2s[w][l] = s2_own; e2s[w][l] = e2_own; }
    }
    __syncwarp();

    // ---- Stage B: lane l -> f3[l], f4[l]; out vector ----
    float e4_own = 0.f, a3o = 0.f, a4o = 0.f;
    {
        float a3 = 0.f, a4 = 0.f;
        const float4* r3 = (const float4*)(sw3 + ll * WPAD);
        const float4* r4 = (const float4*)(sw4 + ll * WPAD);
        const float4* sv = (const float4*)(s2s[w]);
        #pragma unroll
        for (int g = 0; g < 5; g++) {
            float4 A = r3[g], Bv = r4[g], S = sv[g];
            a3 = fmaf(A.x,  S.x, a3); a3 = fmaf(A.y,  S.y, a3);
            a3 = fmaf(A.z,  S.z, a3); a3 = fmaf(A.w,  S.w, a3);
            a4 = fmaf(Bv.x, S.x, a4); a4 = fmaf(Bv.y, S.y, a4);
            a4 = fmaf(Bv.z, S.z, a4); a4 = fmaf(Bv.w, S.w, a4);
        }
        float f3 = tanhf(a3);
        float f4 = tanhf(a4);
        e4_own = expf(f4);
        float s1e = p1_own * e4_own;
        float t1  = s1e + f3;
        a3o = 1.f - f3 * f3;
        a4o = s1e * (1.f - f4 * f4);
        if (act) {
            out_vec[b * DV + l]       = t1;
            out_vec[b * DV + HBV + l] = s2_own;
        }
    }

    // ---- J21 row l (per-lane coeffs, float4 rows) -> smem + bottom output row ----
    {
        const float4* r1 = (const float4*)(sw1 + ll * WPAD);
        const float4* r2 = (const float4*)(sw2 + ll * WPAD);
        float4* js = (float4*)(j21s[w] + ll * HBV);
        float4* bl = (float4*)(jt + (HBV + ll) * DV);         // bottom-left
        float4* br = (float4*)(jt + (HBV + ll) * DV + HBV);   // bottom-right
        #pragma unroll
        for (int g = 0; g < 5; g++) {
            float4 A = r1[g], Bv = r2[g], v;
            v.x = fmaf(b1o, A.x, b2o * Bv.x);
            v.y = fmaf(b1o, A.y, b2o * Bv.y);
            v.z = fmaf(b1o, A.z, b2o * Bv.z);
            v.w = fmaf(b1o, A.w, b2o * Bv.w);
            if (act) {
                js[g] = v;
                bl[g] = v;
                float4 z;
                z.x = (l == 4 * g + 0) ? e2_own : 0.f;
                z.y = (l == 4 * g + 1) ? e2_own : 0.f;
                z.z = (l == 4 * g + 2) ? e2_own : 0.f;
                z.w = (l == 4 * g + 3) ? e2_own : 0.f;
                br[g] = z;
            }
        }
    }

    // ---- JJ12 row l -> regs; top-right = jjrow * e2vec ----
    float4 jj[5];
    {
        const float4* r3 = (const float4*)(sw3 + ll * WPAD);
        const float4* r4 = (const float4*)(sw4 + ll * WPAD);
        const float4* ev = (const float4*)(e2s[w]);   // broadcast
        float4* tr = (float4*)(jt + ll * DV + HBV);
        #pragma unroll
        for (int g = 0; g < 5; g++) {
            float4 A = r3[g], Bv = r4[g], E = ev[g], v, t;
            v.x = fmaf(a3o, A.x, a4o * Bv.x);
            v.y = fmaf(a3o, A.y, a4o * Bv.y);
            v.z = fmaf(a3o, A.z, a4o * Bv.z);
            v.w = fmaf(a3o, A.w, a4o * Bv.w);
            jj[g] = v;
            t.x = v.x * E.x; t.y = v.y * E.y;
            t.z = v.z * E.z; t.w = v.w * E.w;
            if (act) tr[g] = t;
        }
    }
    __syncwarp();   // j21s fully written before TL reads

    // ---- Top-left row l: e4*delta + jjrow @ J21 (row-broadcast matmul) ----
    {
        float4 acc[5];
        #pragma unroll
        for (int g = 0; g < 5; g++) acc[g] = make_float4(0.f, 0.f, 0.f, 0.f);

        const float* jjf = (const float*)jj;
        #pragma unroll
        for (int k = 0; k < HBV; k++) {
            float jjk = jjf[k];                        // static after unroll
            const float4* rk = (const float4*)(j21s[w] + k * HBV);  // broadcast
            #pragma unroll
            for (int g = 0; g < 5; g++) {
                float4 r = rk[g];
                acc[g].x = fmaf(jjk, r.x, acc[g].x);
                acc[g].y = fmaf(jjk, r.y, acc[g].y);
                acc[g].z = fmaf(jjk, r.z, acc[g].z);
                acc[g].w = fmaf(jjk, r.w, acc[g].w);
            }
        }
        float4* tl = (float4*)(jt + ll * DV);
        #pragma unroll
        for (int g = 0; g < 5; g++) {
            float4 v = acc[g];
            v.x += (l == 4 * g + 0) ? e4_own : 0.f;
            v.y += (l == 4 * g + 1) ? e4_own : 0.f;
            v.z += (l == 4 * g + 2) ? e4_own : 0.f;
            v.w += (l == 4 * g + 3) ? e4_own : 0.f;
            if (act) tl[g] = v;
        }
    }
}

extern "C" void kernel_launch(void* const* d_in, const int* in_sizes, int n_in,
                              void* d_out, int out_size) {
    const float* x  = (const float*)d_in[0];
    const float* w1 = (const float*)d_in[1];
    const float* w2 = (const float*)d_in[2];
    const float* w3 = (const float*)d_in[3];
    const float* w4 = (const float*)d_in[4];

    const int B = in_sizes[0] / DV;            // 65536
    float* out_vec = (float*)d_out;            // tuple element 0: (B,1,40)
    float* out_jt  = out_vec + (size_t)B * DV; // tuple element 1: (B,40,40)

    ende_kernel<<<B / WARPS, 128>>>(x, w1, w2, w3, w4, out_vec, out_jt);
}

// round 6
// speedup vs baseline: 1.0638x; 1.0638x over previous
#include <cuda_runtime.h>

#define HBV   20
#define DV    40
#define WPAD  28          // padded weight row: 112B, float4-aligned
#define WARPS 4

__global__ __launch_bounds__(128)
void ende_kernel(const float* __restrict__ x,
                 const float* __restrict__ w1g,
                 const float* __restrict__ w2g,
                 const float* __restrict__ w3g,
                 const float* __restrict__ w4g,
                 float* __restrict__ out_vec,
                 float* __restrict__ out_jt)
{
    __shared__ __align__(16) float sw1[HBV * WPAD];
    __shared__ __align__(16) float sw2[HBV * WPAD];
    __shared__ __align__(16) float sw3[HBV * WPAD];
    __shared__ __align__(16) float sw4[HBV * WPAD];
    __shared__ __align__(16) float  p1A[WARPS][HBV];
    __shared__ __align__(16) float  p1B[WARPS][HBV];
    __shared__ __align__(16) float  s2A[WARPS][HBV];
    __shared__ __align__(16) float  s2B[WARPS][HBV];
    __shared__ __align__(16) float4 cfA[WARPS][HBV];   // (b1_e0,b2_e0,b1_e1,b2_e1)
    __shared__ __align__(16) float4 cfB[WARPS][HBV];   // (a3_e0,a4_e0,a3_e1,a4_e1)
    __shared__ __align__(16) float  jjA[WARPS][HBV * HBV];
    __shared__ __align__(16) float  jjB[WARPS][HBV * HBV];

    const int tid = threadIdx.x;

    // Stage weights into padded smem (once per block)
    for (int idx = tid; idx < HBV * HBV; idx += 128) {
        int r = idx / HBV, c = idx % HBV;
        sw1[r * WPAD + c] = w1g[idx];
        sw2[r * WPAD + c] = w2g[idx];
        sw3[r * WPAD + c] = w3g[idx];
        sw4[r * WPAD + c] = w4g[idx];
    }
    __syncthreads();

    const int w = tid >> 5;
    const int l = tid & 31;
    const bool act = (l < HBV);
    const int ll = act ? l : 0;

    const long long b0 = ((long long)blockIdx.x * WARPS + w) * 2;
    const long long b1 = b0 + 1;

    // ---- load x for both elements; publish p1 vectors ----
    float p1_0 = 0.f, p2_0 = 0.f, p1_1 = 0.f, p2_1 = 0.f;
    if (act) {
        p1_0 = x[b0 * DV + l];
        p2_0 = x[b0 * DV + HBV + l];
        p1_1 = x[b1 * DV + l];
        p2_1 = x[b1 * DV + HBV + l];
        p1A[w][l] = p1_0;
        p1B[w][l] = p1_1;
    }
    __syncwarp();

    // ---- Stage A for both elements: shared W1/W2 row reads ----
    float e2_0 = 0.f, e2_1 = 0.f, s2_0 = 0.f, s2_1 = 0.f;
    {
        float a1_0 = 0.f, a2_0 = 0.f, a1_1 = 0.f, a2_1 = 0.f;
        const float4* r1  = (const float4*)(sw1 + ll * WPAD);
        const float4* r2  = (const float4*)(sw2 + ll * WPAD);
        const float4* pv0 = (const float4*)(p1A[w]);
        const float4* pv1 = (const float4*)(p1B[w]);
        #pragma unroll
        for (int g = 0; g < 5; g++) {
            float4 A = r1[g], Bv = r2[g], P0 = pv0[g], P1 = pv1[g];
            a1_0 = fmaf(A.x,  P0.x, a1_0); a1_0 = fmaf(A.y,  P0.y, a1_0);
            a1_0 = fmaf(A.z,  P0.z, a1_0); a1_0 = fmaf(A.w,  P0.w, a1_0);
            a2_0 = fmaf(Bv.x, P0.x, a2_0); a2_0 = fmaf(Bv.y, P0.y, a2_0);
            a2_0 = fmaf(Bv.z, P0.z, a2_0); a2_0 = fmaf(Bv.w, P0.w, a2_0);
            a1_1 = fmaf(A.x,  P1.x, a1_1); a1_1 = fmaf(A.y,  P1.y, a1_1);
            a1_1 = fmaf(A.z,  P1.z, a1_1); a1_1 = fmaf(A.w,  P1.w, a1_1);
            a2_1 = fmaf(Bv.x, P1.x, a2_1); a2_1 = fmaf(Bv.y, P1.y, a2_1);
            a2_1 = fmaf(Bv.z, P1.z, a2_1); a2_1 = fmaf(Bv.w, P1.w, a2_1);
        }
        float f1_0 = tanhf(a1_0), f2_0 = tanhf(a2_0);
        float f1_1 = tanhf(a1_1), f2_1 = tanhf(a2_1);
        e2_0 = expf(f2_0);
        e2_1 = expf(f2_1);
        float p2e_0 = p2_0 * e2_0;
        float p2e_1 = p2_1 * e2_1;
        s2_0 = p2e_0 + f1_0;
        s2_1 = p2e_1 + f1_1;
        if (act) {
            s2A[w][l] = s2_0;
            s2B[w][l] = s2_1;
            cfA[w][l] = make_float4(1.f - f1_0 * f1_0, p2e_0 * (1.f - f2_0 * f2_0),
                                    1.f - f1_1 * f1_1, p2e_1 * (1.f - f2_1 * f2_1));
        }
    }
    __syncwarp();

    // ---- Stage B for both elements: shared W3/W4 row reads; out vectors ----
    float e4_0 = 0.f, e4_1 = 0.f;
    {
        float a3_0 = 0.f, a4_0 = 0.f, a3_1 = 0.f, a4_1 = 0.f;
        const float4* r3  = (const float4*)(sw3 + ll * WPAD);
        const float4* r4  = (const float4*)(sw4 + ll * WPAD);
        const float4* sv0 = (const float4*)(s2A[w]);
        const float4* sv1 = (const float4*)(s2B[w]);
        #pragma unroll
        for (int g = 0; g < 5; g++) {
            float4 A = r3[g], Bv = r4[g], S0 = sv0[g], S1 = sv1[g];
            a3_0 = fmaf(A.x,  S0.x, a3_0); a3_0 = fmaf(A.y,  S0.y, a3_0);
            a3_0 = fmaf(A.z,  S0.z, a3_0); a3_0 = fmaf(A.w,  S0.w, a3_0);
            a4_0 = fmaf(Bv.x, S0.x, a4_0); a4_0 = fmaf(Bv.y, S0.y, a4_0);
            a4_0 = fmaf(Bv.z, S0.z, a4_0); a4_0 = fmaf(Bv.w, S0.w, a4_0);
            a3_1 = fmaf(A.x,  S1.x, a3_1); a3_1 = fmaf(A.y,  S1.y, a3_1);
            a3_1 = fmaf(A.z,  S1.z, a3_1); a3_1 = fmaf(A.w,  S1.w, a3_1);
            a4_1 = fmaf(Bv.x, S1.x, a4_1); a4_1 = fmaf(Bv.y, S1.y, a4_1);
            a4_1 = fmaf(Bv.z, S1.z, a4_1); a4_1 = fmaf(Bv.w, S1.w, a4_1);
        }
        float f3_0 = tanhf(a3_0), f4_0 = tanhf(a4_0);
        float f3_1 = tanhf(a3_1), f4_1 = tanhf(a4_1);
        e4_0 = expf(f4_0);
        e4_1 = expf(f4_1);
        float s1e_0 = p1_0 * e4_0;
        float s1e_1 = p1_1 * e4_1;
        if (act) {
            cfB[w][l] = make_float4(1.f - f3_0 * f3_0, s1e_0 * (1.f - f4_0 * f4_0),
                                    1.f - f3_1 * f3_1, s1e_1 * (1.f - f4_1 * f4_1));
            out_vec[b0 * DV + l]       = s1e_0 + f3_0;
            out_vec[b0 * DV + HBV + l] = s2_0;
            out_vec[b1 * DV + l]       = s1e_1 + f3_1;
            out_vec[b1 * DV + HBV + l] = s2_1;
        }
    }
    __syncwarp();

    float* jt0 = out_jt + b0 * (DV * DV);
    float* jt1 = out_jt + b1 * (DV * DV);

    // ---- Fused J21/JJ12 loop, both elements, shared weight column reads ----
    float J0[HBV], J1[HBV];
    if (act) {
        #pragma unroll
        for (int k = 0; k < HBV; k++) {
            float4 cA = cfA[w][k];                  // broadcast: 1 wf, 2 elems
            float4 cB = cfB[w][k];                  // broadcast: 1 wf, 2 elems
            float w1v = sw1[k * WPAD + l];          // shared column reads
            float w2v = sw2[k * WPAD + l];
            float w3v = sw3[k * WPAD + l];
            float w4v = sw4[k * WPAD + l];

            float v0 = fmaf(cA.x, w1v, cA.y * w2v); // J21 rows
            float v1 = fmaf(cA.z, w1v, cA.w * w2v);
            J0[k] = v0;
            J1[k] = v1;
            jt0[(HBV + k) * DV + l] = v0;
            jt1[(HBV + k) * DV + l] = v1;
            jt0[(HBV + k) * DV + HBV + l] = (l == k) ? e2_0 : 0.f;
            jt1[(HBV + k) * DV + HBV + l] = (l == k) ? e2_1 : 0.f;

            float u0 = fmaf(cB.x, w3v, cB.y * w4v); // JJ12 rows
            float u1 = fmaf(cB.z, w3v, cB.w * w4v);
            jjA[w][k * HBV + l] = u0;
            jjB[w][k * HBV + l] = u1;
            jt0[k * DV + HBV + l] = u0 * e2_0;      // TR = JJ12 * diag(e2)
            jt1[k * DV + HBV + l] = u1 * e2_1;
        }
    }
    __syncwarp();

    // ---- Top-left blocks: diag(e4) + JJ12 @ J21, element 0 then 1 ----
    if (act) {
        #pragma unroll 4
        for (int i = 0; i < HBV; i++) {
            const float4* rv = (const float4*)(jjA[w] + i * HBV);
            float m = 0.f;
            #pragma unroll
            for (int g = 0; g < 5; g++) {
                float4 c = rv[g];
                m = fmaf(c.x, J0[4 * g + 0], m);
                m = fmaf(c.y, J0[4 * g + 1], m);
                m = fmaf(c.z, J0[4 * g + 2], m);
                m = fmaf(c.w, J0[4 * g + 3], m);
            }
            if (i == l) m += e4_0;
            jt0[i * DV + l] = m;
        }
        #pragma unroll 4
        for (int i = 0; i < HBV; i++) {
            const float4* rv = (const float4*)(jjB[w] + i * HBV);
            float m = 0.f;
            #pragma unroll
            for (int g = 0; g < 5; g++) {
                float4 c = rv[g];
                m = fmaf(c.x, J1[4 * g + 0], m);
                m = fmaf(c.y, J1[4 * g + 1], m);
                m = fmaf(c.z, J1[4 * g + 2], m);
                m = fmaf(c.w, J1[4 * g + 3], m);
            }
            if (i == l) m += e4_1;
            jt1[i * DV + l] = m;
        }
    }
}

extern "C" void kernel_launch(void* const* d_in, const int* in_sizes, int n_in,
                              void* d_out, int out_size) {
    const float* x  = (const float*)d_in[0];
    const float* w1 = (const float*)d_in[1];
    const float* w2 = (const float*)d_in[2];
    const float* w3 = (const float*)d_in[3];
    const float* w4 = (const float*)d_in[4];

    const int B = in_sizes[0] / DV;            // 65536
    float* out_vec = (float*)d_out;            // tuple element 0: (B,1,40)
    float* out_jt  = out_vec + (size_t)B * DV; // tuple element 1: (B,40,40)

    const int blocks = B / (WARPS * 2);        // 8192
    ende_kernel<<<blocks, 128>>>(x, w1, w2, w3, w4, out_vec, out_jt);
}

// round 7
// speedup vs baseline: 1.2174x; 1.1443x over previous
#include <cuda_runtime.h>

#define HBV   20
#define DV    40
#define WPAD  28            // padded weight row: 112B, float4-aligned
#define EPB   16            // elements per block
#define NTHR  320           // 16 elements * 20 columns
#define JJS   404           // jj element stride (floats): bank-disjoint across elems

__global__ __launch_bounds__(NTHR, 4)
void ende_kernel(const float* __restrict__ x,
                 const float* __restrict__ w1g,
                 const float* __restrict__ w2g,
                 const float* __restrict__ w3g,
                 const float* __restrict__ w4g,
                 float* __restrict__ out_vec,
                 float* __restrict__ out_jt)
{
    __shared__ __align__(16) float  sw1[HBV * WPAD];
    __shared__ __align__(16) float  sw2[HBV * WPAD];
    __shared__ __align__(16) float  sw3[HBV * WPAD];
    __shared__ __align__(16) float  sw4[HBV * WPAD];
    __shared__ __align__(16) float  p1s[EPB][HBV];
    __shared__ __align__(16) float  s2s[EPB][HBV];
    __shared__ __align__(16) float4 cfs[EPB][HBV];   // (b1,b2,a3,a4) per row k
    __shared__ __align__(16) float  jjs[EPB * JJS];  // JJ12 per element

    const int tid = threadIdx.x;

    // Stage weights into padded smem (once per block)
    for (int idx = tid; idx < HBV * HBV; idx += NTHR) {
        int r = idx / HBV, cc = idx % HBV;
        sw1[r * WPAD + cc] = w1g[idx];
        sw2[r * WPAD + cc] = w2g[idx];
        sw3[r * WPAD + cc] = w3g[idx];
        sw4[r * WPAD + cc] = w4g[idx];
    }

    const int e = tid / HBV;          // element slot within block
    const int c = tid - e * HBV;      // column / row index owned by this lane
    const long long b = (long long)blockIdx.x * EPB + e;

    // ---- load x; publish p1 vector ----
    const float p1_own = x[b * DV + c];
    const float p2_own = x[b * DV + HBV + c];
    p1s[e][c] = p1_own;
    __syncthreads();

    // ---- Stage A: lane -> f1[c], f2[c] of element e (row-c matvec) ----
    float e2_own, s2_own;
    {
        float a1 = 0.f, a2 = 0.f;
        const float4* r1 = (const float4*)(sw1 + c * WPAD);
        const float4* r2 = (const float4*)(sw2 + c * WPAD);
        const float4* pv = (const float4*)(p1s[e]);
        #pragma unroll
        for (int g = 0; g < 5; g++) {
            float4 A = r1[g], Bv = r2[g], P = pv[g];
            a1 = fmaf(A.x,  P.x, a1); a1 = fmaf(A.y,  P.y, a1);
            a1 = fmaf(A.z,  P.z, a1); a1 = fmaf(A.w,  P.w, a1);
            a2 = fmaf(Bv.x, P.x, a2); a2 = fmaf(Bv.y, P.y, a2);
            a2 = fmaf(Bv.z, P.z, a2); a2 = fmaf(Bv.w, P.w, a2);
        }
        float f1 = tanhf(a1);
        float f2 = tanhf(a2);
        e2_own = expf(f2);
        float p2e = p2_own * e2_own;
        s2_own = p2e + f1;
        s2s[e][c] = s2_own;
        ((float2*)&cfs[e][c])[0] = make_float2(1.f - f1 * f1,
                                               p2e * (1.f - f2 * f2));
    }
    __syncthreads();

    // ---- Stage B: lane -> f3[c], f4[c]; out vector ----
    float e4_own;
    {
        float a3 = 0.f, a4 = 0.f;
        const float4* r3 = (const float4*)(sw3 + c * WPAD);
        const float4* r4 = (const float4*)(sw4 + c * WPAD);
        const float4* sv = (const float4*)(s2s[e]);
        #pragma unroll
        for (int g = 0; g < 5; g++) {
            float4 A = r3[g], Bv = r4[g], S = sv[g];
            a3 = fmaf(A.x,  S.x, a3); a3 = fmaf(A.y,  S.y, a3);
            a3 = fmaf(A.z,  S.z, a3); a3 = fmaf(A.w,  S.w, a3);
            a4 = fmaf(Bv.x, S.x, a4); a4 = fmaf(Bv.y, S.y, a4);
            a4 = fmaf(Bv.z, S.z, a4); a4 = fmaf(Bv.w, S.w, a4);
        }
        float f3 = tanhf(a3);
        float f4 = tanhf(a4);
        e4_own = expf(f4);
        float s1e = p1_own * e4_own;
        ((float2*)&cfs[e][c])[1] = make_float2(1.f - f3 * f3,
                                               s1e * (1.f - f4 * f4));
        out_vec[b * DV + c]       = s1e + f3;
        out_vec[b * DV + HBV + c] = s2_own;
    }
    __syncthreads();

    float* jt = out_jt + b * (DV * DV);
    float* jje = jjs + e * JJS;

    // ---- Fused loop over k: J21 row k -> regs + BL; BR; JJ12 row k -> smem + TR ----
    float J21r[HBV];
    #pragma unroll
    for (int k = 0; k < HBV; k++) {
        float4 cf  = cfs[e][k];            // per-element broadcast
        float  w1v = sw1[k * WPAD + c];    // same row k for all lanes
        float  w2v = sw2[k * WPAD + c];
        float  w3v = sw3[k * WPAD + c];
        float  w4v = sw4[k * WPAD + c];

        float v = fmaf(cf.x, w1v, cf.y * w2v);   // J21[k, c]
        J21r[k] = v;
        jt[(HBV + k) * DV + c]       = v;
        jt[(HBV + k) * DV + HBV + c] = (c == k) ? e2_own : 0.f;

        float u = fmaf(cf.z, w3v, cf.w * w4v);   // JJ12[k, c]
        jje[k * HBV + c]       = u;
        jt[k * DV + HBV + c]   = u * e2_own;     // TR = JJ12 * diag(e2)
    }
    __syncthreads();

    // ---- Top-left: TL[i, c] = e4[i] delta_ic + sum_k JJ12[i,k] * J21[k,c] ----
    #pragma unroll 4
    for (int i = 0; i < HBV; i++) {
        const float4* rv = (const float4*)(jje + i * HBV);   // row broadcast
        float m = 0.f;
        #pragma unroll
        for (int g = 0; g < 5; g++) {
            float4 r = rv[g];
            m = fmaf(r.x, J21r[4 * g + 0], m);
            m = fmaf(r.y, J21r[4 * g + 1], m);
            m = fmaf(r.z, J21r[4 * g + 2], m);
            m = fmaf(r.w, J21r[4 * g + 3], m);
        }
        if (i == c) m += e4_own;
        jt[i * DV + c] = m;
    }
}

extern "C" void kernel_launch(void* const* d_in, const int* in_sizes, int n_in,
                              void* d_out, int out_size) {
    const float* x  = (const float*)d_in[0];
    const float* w1 = (const float*)d_in[1];
    const float* w2 = (const float*)d_in[2];
    const float* w3 = (const float*)d_in[3];
    const float* w4 = (const float*)d_in[4];

    const int B = in_sizes[0] / DV;            // 65536
    float* out_vec = (float*)d_out;            // tuple element 0: (B,1,40)
    float* out_jt  = out_vec + (size_t)B * DV; // tuple element 1: (B,40,40)

    ende_kernel<<<B / EPB, NTHR>>>(x, w1, w2, w3, w4, out_vec, out_jt);
}